// round 11
// baseline (speedup 1.0000x reference)
#include <cuda_runtime.h>
#include <cuda_fp16.h>
#include <mma.h>
#include <cstdint>

using namespace nvcuda;

#define BATCH 256
#define NSEQ  512
#define QDIM  2048
#define VDIM  2048
#define ADIM  1024
#define MROWS (BATCH * NSEQ)   // 131072

// ---- scratch (module-scope device arrays; no runtime allocation) ----
__device__ __half g_yh[(size_t)MROWS * VDIM];      // 512 MB, Y fp16 (written by logits_mma ntile==0)
__device__ __half g_wvh[(size_t)VDIM * ADIM];      // 4 MB, W_vis in fp16
__device__ float  g_x2att[BATCH * ADIM];           // 1 MB
__device__ float  g_part[8 * MROWS];               // 4 MB logit partials
__device__ float  g_w[BATCH * NSEQ];               // softmax weights

// ======================= async-copy helpers =======================
__device__ __forceinline__ uint32_t smem_u32(const void* p) {
    uint32_t a;
    asm("{ .reg .u64 t; cvta.to.shared.u64 t, %1; cvt.u32.u64 %0, t; }" : "=r"(a) : "l"(p));
    return a;
}
__device__ __forceinline__ void cp16(uint32_t dst, const void* g) {
    asm volatile("cp.async.cg.shared.global [%0], [%1], 16;" :: "r"(dst), "l"(g));
}
#define CP_COMMIT() asm volatile("cp.async.commit_group;" ::: "memory")
#define CP_WAIT(n)  asm volatile("cp.async.wait_group %0;" :: "n"(n) : "memory")

// ======================= fp32 -> fp16 conversion (W_vis only, 4 MB) =======================
__global__ __launch_bounds__(256)
void cvt_w(const float* __restrict__ W)
{
    size_t i = ((size_t)blockIdx.x * 256 + threadIdx.x) * 8;
    float4 v0 = *(const float4*)(W + i);
    float4 v1 = *(const float4*)(W + i + 4);
    __half2 h0 = __floats2half2_rn(v0.x, v0.y);
    __half2 h1 = __floats2half2_rn(v0.z, v0.w);
    __half2 h2 = __floats2half2_rn(v1.x, v1.y);
    __half2 h3 = __floats2half2_rn(v1.z, v1.w);
    uint4 packed;
    packed.x = *(uint32_t*)&h0; packed.y = *(uint32_t*)&h1;
    packed.z = *(uint32_t*)&h2; packed.w = *(uint32_t*)&h3;
    *(uint4*)(g_wvh + i) = packed;
}

// ======================= fused logits GEMM (fp16 wmma, inline A cvt) =======================
// part[nt, m] = sum_a relu( (Y @ W_vis)[m, a] + x2att[b(m), a] ) * W_map[a]
// A (Y, fp32) via LDG float4 -> fp16 regs -> STS 2-buffer ring.
// B (W_vis fp16) via 4-stage cp.async ring.
// ntile==0 CTAs persist the converted A tiles to g_yh for attend_k.
constexpr int BM = 128, BN = 128, BK = 32;
constexpr int NK = QDIM / BK;                 // 64
constexpr int APH = 40;                       // A pitch in halves (80 B rows)
constexpr int BPH = 136;                      // B pitch in halves (272 B rows)
constexpr int A_BYTES = BM * APH * 2;         // 10240 per A buffer
constexpr int B_BYTES = BK * BPH * 2;         // 8704 per B stage
constexpr int B_BASE  = 2 * A_BYTES;          // B ring after the 2 A buffers
constexpr int EPI_P = BN + 4;
constexpr size_t DSMEM_GEMM = (size_t)B_BASE + 4 * B_BYTES;       // 55296
constexpr size_t DSMEM_EPI  = (size_t)BM * EPI_P * 4;             // 67584
constexpr size_t DSMEM = DSMEM_GEMM > DSMEM_EPI ? DSMEM_GEMM : DSMEM_EPI;

__global__ __launch_bounds__(256, 2)
void logits_mma(const float* __restrict__ Y, const float* __restrict__ Wmap)
{
    extern __shared__ char smc[];
    __shared__ float xs[BN], ws[BN];
    __shared__ float psum[BM][2];

    const int tid  = threadIdx.x;
    const int warp = tid >> 5;
    const int wr   = warp & 3;          // 32-row slab
    const int wc   = warp >> 2;         // 64-col slab

    const int ntile = blockIdx.x;       // 0..7 fastest (Y-tile L2 reuse)
    const int mtile = blockIdx.y;       // 0..1023
    const int a0    = ntile * BN;
    const size_t row0 = (size_t)mtile * BM;
    const int b     = mtile >> 2;

    if (tid < BN) {
        xs[tid] = g_x2att[(size_t)b * ADIM + a0 + tid];
        ws[tid] = Wmap[a0 + tid];
    }

    const float*  Ab = Y + row0 * QDIM;       // fp32 A
    const __half* Bb = g_wvh;
    const uint32_t sbase = smem_u32(smc);

    // per-thread A chunk coords: 1024 float4 chunks, 4 per thread
    const int ar = tid >> 3;            // row base (stride 32 over i)
    const int ac = tid & 7;             // float4 column (0..7)

    // ---- A: LDG float4 -> packed half2 regs ----
    uint32_t apk[8];
    auto ldg_cvt_a = [&](int st) {
        int k0 = st * BK;
        #pragma unroll
        for (int i = 0; i < 4; i++) {
            int r = ar + i * 32;
            float4 v = *(const float4*)(Ab + (size_t)r * QDIM + k0 + ac * 4);
            __half2 h0 = __floats2half2_rn(v.x, v.y);
            __half2 h1 = __floats2half2_rn(v.z, v.w);
            apk[i * 2]     = *(uint32_t*)&h0;
            apk[i * 2 + 1] = *(uint32_t*)&h1;
        }
    };
    auto sts_a = [&](int buf) {        // buf MUST be 0 or 1
        char* base = smc + buf * A_BYTES;
        #pragma unroll
        for (int i = 0; i < 4; i++) {
            int r = ar + i * 32;
            *(uint2*)(base + r * (APH * 2) + ac * 8) = make_uint2(apk[i*2], apk[i*2+1]);
        }
    };
    auto stg_yh = [&](int st) {
        int k0 = st * BK;
        #pragma unroll
        for (int i = 0; i < 4; i++) {
            int r = ar + i * 32;
            *(uint2*)(g_yh + (row0 + r) * QDIM + k0 + ac * 4) = make_uint2(apk[i*2], apk[i*2+1]);
        }
    };

    // ---- B: cp.async stage loader (512 chunks, 2 per thread) ----
    auto load_b = [&](int st) {
        uint32_t base = sbase + (uint32_t)(B_BASE + (st & 3) * B_BYTES);
        int k0 = st * BK;
        #pragma unroll
        for (int i = 0; i < 2; i++) {
            int idx = tid + i * 256;
            int r = idx >> 4, c = idx & 15;
            cp16(base + r * (BPH * 2) + c * 16,
                 Bb + (size_t)(k0 + r) * ADIM + a0 + c * 8);
        }
    };

    wmma::fragment<wmma::accumulator, 16, 16, 16, float> acc[2][4];
    #pragma unroll
    for (int i = 0; i < 2; i++)
        #pragma unroll
        for (int j = 0; j < 4; j++)
            wmma::fill_fragment(acc[i][j], 0.0f);

    // ---- prologue ----
    ldg_cvt_a(0);
    load_b(0); CP_COMMIT();
    load_b(1); CP_COMMIT();
    load_b(2); CP_COMMIT();
    sts_a(0);
    if (ntile == 0) stg_yh(0);
    ldg_cvt_a(1);

    #pragma unroll 1
    for (int kt = 0; kt < NK; kt++) {
        CP_WAIT(2);
        __syncthreads();        // B(kt) + Abuf[kt&1] ready; prior compute done (WAR safe)

        if (kt + 1 < NK) {
            sts_a((kt + 1) & 1);               // FIX: buffer index, not stage number
            if (ntile == 0) stg_yh(kt + 1);
        }
        if (kt + 2 < NK) ldg_cvt_a(kt + 2);
        if (kt + 3 < NK) load_b(kt + 3);
        CP_COMMIT();

        const __half* sA = (const __half*)(smc + (kt & 1) * A_BYTES);
        const __half* sB = (const __half*)(smc + B_BASE + (kt & 3) * B_BYTES);

        #pragma unroll
        for (int kk = 0; kk < BK; kk += 16) {
            wmma::fragment<wmma::matrix_a, 16, 16, 16, __half, wmma::row_major> af[2];
            wmma::fragment<wmma::matrix_b, 16, 16, 16, __half, wmma::row_major> bf[4];
            #pragma unroll
            for (int i = 0; i < 2; i++)
                wmma::load_matrix_sync(af[i], sA + (wr * 32 + i * 16) * APH + kk, APH);
            #pragma unroll
            for (int j = 0; j < 4; j++)
                wmma::load_matrix_sync(bf[j], sB + kk * BPH + wc * 64 + j * 16, BPH);
            #pragma unroll
            for (int i = 0; i < 2; i++)
                #pragma unroll
                for (int j = 0; j < 4; j++)
                    wmma::mma_sync(acc[i][j], af[i], bf[j], acc[i][j]);
        }
    }

    __syncthreads();      // all compute done before Epi overwrites buffers

    float* Epi = (float*)smc;
    #pragma unroll
    for (int i = 0; i < 2; i++)
        #pragma unroll
        for (int j = 0; j < 4; j++)
            wmma::store_matrix_sync(Epi + (wr * 32 + i * 16) * EPI_P + wc * 64 + j * 16,
                                    acc[i][j], EPI_P, wmma::mem_row_major);
    __syncthreads();

    const int r = tid & 127;
    const int half = tid >> 7;
    const float* er = Epi + r * EPI_P + half * 64;
    float s = 0.0f;
    #pragma unroll 8
    for (int j = 0; j < 64; j++) {
        int c = half * 64 + j;
        float v = er[j] + xs[c];
        s += fmaxf(v, 0.0f) * ws[c];
    }
    psum[r][half] = s;
    __syncthreads();
    if (tid < BM)
        g_part[(size_t)ntile * MROWS + row0 + tid] = psum[tid][0] + psum[tid][1];
}

// ======================= X2att = X @ W_ques + b_ques (tf32) =======================
constexpr int XBM = 128, XBN = 128, XBK = 32;
constexpr int XALD = XBK + 4, XBLD = XBN + 4, XELD = XBN + 4;
constexpr size_t XSMEM = ((size_t)XBM * XELD * 4 > (size_t)(XBM * XALD + XBK * XBLD) * 4)
                       ? (size_t)XBM * XELD * 4 : (size_t)(XBM * XALD + XBK * XBLD) * 4;

__global__ __launch_bounds__(256)
void x2att_gemm(const float* __restrict__ X, const float* __restrict__ Wq,
                const float* __restrict__ bias)
{
    extern __shared__ float smem[];
    float* As = smem;
    float* Bs = smem + XBM * XALD;
    float* Epi = smem;

    const int tid = threadIdx.x;
    const int warp = tid >> 5;
    const int wr = warp & 3, wc = warp >> 2;
    const int a0 = blockIdx.x * XBN;
    const int row0 = blockIdx.y * XBM;
    const float* Arow = X + (size_t)row0 * QDIM;

    wmma::fragment<wmma::accumulator, 16, 16, 8, float> c[2][4];
    #pragma unroll
    for (int i = 0; i < 2; i++)
        #pragma unroll
        for (int j = 0; j < 4; j++) wmma::fill_fragment(c[i][j], 0.0f);

    for (int k0 = 0; k0 < QDIM; k0 += XBK) {
        #pragma unroll
        for (int i = 0; i < 4; i++) {
            int idx = tid + i * 256;
            int r = idx >> 3, cc = (idx & 7) << 2;
            float4 v = *(const float4*)(Arow + (size_t)r * QDIM + k0 + cc);
            float* dst = As + r * XALD + cc;
            dst[0] = wmma::__float_to_tf32(v.x); dst[1] = wmma::__float_to_tf32(v.y);
            dst[2] = wmma::__float_to_tf32(v.z); dst[3] = wmma::__float_to_tf32(v.w);
        }
        #pragma unroll
        for (int i = 0; i < 4; i++) {
            int idx = tid + i * 256;
            int r = idx >> 5, cc = (idx & 31) << 2;
            float4 v = *(const float4*)(Wq + (size_t)(k0 + r) * ADIM + a0 + cc);
            float* dst = Bs + r * XBLD + cc;
            dst[0] = wmma::__float_to_tf32(v.x); dst[1] = wmma::__float_to_tf32(v.y);
            dst[2] = wmma::__float_to_tf32(v.z); dst[3] = wmma::__float_to_tf32(v.w);
        }
        __syncthreads();
        #pragma unroll
        for (int kk = 0; kk < XBK; kk += 8) {
            wmma::fragment<wmma::matrix_a, 16, 16, 8, wmma::precision::tf32, wmma::row_major> af[2];
            wmma::fragment<wmma::matrix_b, 16, 16, 8, wmma::precision::tf32, wmma::row_major> bf[4];
            #pragma unroll
            for (int i = 0; i < 2; i++)
                wmma::load_matrix_sync(af[i], As + (wr * 32 + i * 16) * XALD + kk, XALD);
            #pragma unroll
            for (int j = 0; j < 4; j++)
                wmma::load_matrix_sync(bf[j], Bs + kk * XBLD + wc * 64 + j * 16, XBLD);
            #pragma unroll
            for (int i = 0; i < 2; i++)
                #pragma unroll
                for (int j = 0; j < 4; j++)
                    wmma::mma_sync(c[i][j], af[i], bf[j], c[i][j]);
        }
        __syncthreads();
    }
    #pragma unroll
    for (int i = 0; i < 2; i++)
        #pragma unroll
        for (int j = 0; j < 4; j++)
            wmma::store_matrix_sync(Epi + (wr * 32 + i * 16) * XELD + wc * 64 + j * 16,
                                    c[i][j], XELD, wmma::mem_row_major);
    __syncthreads();
    for (int e = tid; e < XBM * XBN; e += 256) {
        int r = e >> 7, cc = e & 127;
        g_x2att[(size_t)(row0 + r) * ADIM + a0 + cc] = Epi[r * XELD + cc] + bias[a0 + cc];
    }
}

// ======================= softmax + attend =======================
__global__ void softmax_k()
{
    __shared__ float red[256];
    const int b = blockIdx.x, t = threadIdx.x;
    float v0 = 0.0f, v1 = 0.0f;
    #pragma unroll
    for (int p = 0; p < 8; p++) {
        const float* P = g_part + (size_t)p * MROWS + (size_t)b * NSEQ;
        v0 += P[t]; v1 += P[t + 256];
    }
    red[t] = fmaxf(v0, v1);
    __syncthreads();
    for (int s = 128; s > 0; s >>= 1) { if (t < s) red[t] = fmaxf(red[t], red[t + s]); __syncthreads(); }
    float m = red[0];
    __syncthreads();
    float e0 = __expf(v0 - m), e1 = __expf(v1 - m);
    red[t] = e0 + e1;
    __syncthreads();
    for (int s = 128; s > 0; s >>= 1) { if (t < s) red[t] += red[t + s]; __syncthreads(); }
    float inv = 1.0f / red[0];
    g_w[b * NSEQ + t]       = e0 * inv;
    g_w[b * NSEQ + t + 256] = e1 * inv;
}

// reads fp16 Y scratch (written by logits_mma ntile==0 CTAs)
__global__ __launch_bounds__(128)
void attend_k(float* __restrict__ out)
{
    __shared__ float w[NSEQ];
    const int b = blockIdx.y;
    const int v = blockIdx.x * 1024 + threadIdx.x * 8;

    for (int i = threadIdx.x; i < NSEQ; i += 128) w[i] = g_w[b * NSEQ + i];
    __syncthreads();

    const __half* Yb = g_yh + (size_t)b * NSEQ * VDIM + v;
    float acc[8] = {0.f};
    #pragma unroll 4
    for (int n = 0; n < NSEQ; n++) {
        uint4 p = *(const uint4*)(Yb + (size_t)n * VDIM);
        float wn = w[n];
        float2 f0 = __half22float2(*(__half2*)&p.x);
        float2 f1 = __half22float2(*(__half2*)&p.y);
        float2 f2 = __half22float2(*(__half2*)&p.z);
        float2 f3 = __half22float2(*(__half2*)&p.w);
        acc[0] += wn * f0.x; acc[1] += wn * f0.y;
        acc[2] += wn * f1.x; acc[3] += wn * f1.y;
        acc[4] += wn * f2.x; acc[5] += wn * f2.y;
        acc[6] += wn * f3.x; acc[7] += wn * f3.y;
    }
    float4 o0 = make_float4(acc[0], acc[1], acc[2], acc[3]);
    float4 o1 = make_float4(acc[4], acc[5], acc[6], acc[7]);
    *(float4*)(out + (size_t)b * VDIM + v)     = o0;
    *(float4*)(out + (size_t)b * VDIM + v + 4) = o1;
}

// ======================= launch =======================
extern "C" void kernel_launch(void* const* d_in, const int* in_sizes, int n_in,
                              void* d_out, int out_size)
{
    const float* X      = (const float*)d_in[0];
    const float* Y      = (const float*)d_in[1];
    const float* W_vis  = (const float*)d_in[2];
    const float* W_ques = (const float*)d_in[3];
    const float* b_ques = (const float*)d_in[4];
    const float* W_map  = (const float*)d_in[5];
    // d_in[6] = b_map: cancels under softmax shift-invariance.
    float* out = (float*)d_out;

    cudaFuncSetAttribute(x2att_gemm, cudaFuncAttributeMaxDynamicSharedMemorySize, (int)XSMEM);
    cudaFuncSetAttribute(logits_mma, cudaFuncAttributeMaxDynamicSharedMemorySize, (int)DSMEM);

    cvt_w<<<(size_t)VDIM * ADIM / (256 * 8), 256>>>(W_vis);
    x2att_gemm<<<dim3(ADIM / XBN, BATCH / XBM), 256, XSMEM>>>(X, W_ques, b_ques);
    logits_mma<<<dim3(ADIM / BN, MROWS / BM), 256, DSMEM>>>(Y, W_map);
    softmax_k<<<BATCH, 256>>>();
    attend_k<<<dim3(VDIM / 1024, BATCH), 128>>>(out);
}

// round 12
// speedup vs baseline: 1.3144x; 1.3144x over previous
#include <cuda_runtime.h>
#include <cuda_fp16.h>
#include <mma.h>
#include <cstdint>

using namespace nvcuda;

#define BATCH 256
#define NSEQ  512
#define QDIM  2048
#define VDIM  2048
#define ADIM  1024
#define MROWS (BATCH * NSEQ)   // 131072

// ---- scratch (module-scope device arrays; no runtime allocation) ----
__device__ __half g_yh[(size_t)MROWS * VDIM];      // 512 MB, Y in fp16
__device__ __half g_wvh[(size_t)VDIM * ADIM];      // 4 MB, W_vis in fp16
__device__ __half g_xh[(size_t)BATCH * QDIM];      // 1 MB, X in fp16
__device__ __half g_wqh[(size_t)QDIM * ADIM];      // 4 MB, W_ques in fp16
__device__ float  g_x2att[BATCH * ADIM];           // 1 MB
__device__ float  g_part[8 * MROWS];               // 4 MB logit partials
__device__ float  g_w[BATCH * NSEQ];               // softmax weights

// ======================= async-copy helpers =======================
__device__ __forceinline__ uint32_t smem_u32(const void* p) {
    uint32_t a;
    asm("{ .reg .u64 t; cvta.to.shared.u64 t, %1; cvt.u32.u64 %0, t; }" : "=r"(a) : "l"(p));
    return a;
}
__device__ __forceinline__ void cp16(uint32_t dst, const void* g) {
    asm volatile("cp.async.cg.shared.global [%0], [%1], 16;" :: "r"(dst), "l"(g));
}
#define CP_COMMIT() asm volatile("cp.async.commit_group;" ::: "memory")
#define CP_WAIT(n)  asm volatile("cp.async.wait_group %0;" :: "n"(n) : "memory")

// ======================= fp32 -> fp16 conversion passes =======================
__device__ __forceinline__ void cvt8(const float* __restrict__ src, __half* __restrict__ dst, size_t i)
{
    float4 v0 = *(const float4*)(src + i);
    float4 v1 = *(const float4*)(src + i + 4);
    __half2 h0 = __floats2half2_rn(v0.x, v0.y);
    __half2 h1 = __floats2half2_rn(v0.z, v0.w);
    __half2 h2 = __floats2half2_rn(v1.x, v1.y);
    __half2 h3 = __floats2half2_rn(v1.z, v1.w);
    uint4 packed;
    packed.x = *(uint32_t*)&h0; packed.y = *(uint32_t*)&h1;
    packed.z = *(uint32_t*)&h2; packed.w = *(uint32_t*)&h3;
    *(uint4*)(dst + i) = packed;
}

__global__ __launch_bounds__(256) void cvt_y(const float* __restrict__ Y)
{ cvt8(Y, g_yh, ((size_t)blockIdx.x * 256 + threadIdx.x) * 8); }

__global__ __launch_bounds__(256) void cvt_w(const float* __restrict__ W)
{ cvt8(W, g_wvh, ((size_t)blockIdx.x * 256 + threadIdx.x) * 8); }

__global__ __launch_bounds__(256) void cvt_x(const float* __restrict__ X)
{ cvt8(X, g_xh, ((size_t)blockIdx.x * 256 + threadIdx.x) * 8); }

__global__ __launch_bounds__(256) void cvt_wq(const float* __restrict__ W)
{ cvt8(W, g_wqh, ((size_t)blockIdx.x * 256 + threadIdx.x) * 8); }

// ======================= shared GEMM tiling constants =======================
constexpr int BM = 128, BN = 128, BK = 32;
constexpr int NK = QDIM / BK;                 // 64
constexpr int APH = 40;                       // A pitch in halves (80 B rows)
constexpr int BPH = 136;                      // B pitch in halves (272 B rows)
constexpr int A_BYTES = BM * APH * 2;         // 10240
constexpr int B_BYTES = BK * BPH * 2;         // 8704
constexpr int STAGE_BYTES = A_BYTES + B_BYTES;  // 18944
constexpr int EPI_P = BN + 4;
constexpr size_t DSMEM_GEMM = (size_t)4 * STAGE_BYTES;            // 75776
constexpr size_t DSMEM_EPI  = (size_t)BM * EPI_P * 4;             // 67584
constexpr size_t DSMEM = DSMEM_GEMM > DSMEM_EPI ? DSMEM_GEMM : DSMEM_EPI;

// ======================= fused logits GEMM (R8-proven) =======================
// part[nt, m] = sum_a relu( (Y @ W_vis)[m, a] + x2att[b(m), a] ) * W_map[a]
__global__ __launch_bounds__(256, 2)
void logits_mma(const float* __restrict__ Wmap)
{
    extern __shared__ char smc[];
    __shared__ float xs[BN], ws[BN];
    __shared__ float psum[BM][2];

    const int tid  = threadIdx.x;
    const int warp = tid >> 5;
    const int wr   = warp & 3;
    const int wc   = warp >> 2;

    const int ntile = blockIdx.x;       // 0..7 fastest (Y-tile L2 reuse)
    const int mtile = blockIdx.y;       // 0..1023
    const int a0    = ntile * BN;
    const size_t row0 = (size_t)mtile * BM;
    const int b     = mtile >> 2;

    if (tid < BN) {
        xs[tid] = g_x2att[(size_t)b * ADIM + a0 + tid];
        ws[tid] = Wmap[a0 + tid];
    }

    const __half* Ab = g_yh + row0 * QDIM;
    const __half* Bb = g_wvh;
    const uint32_t sbase = smem_u32(smc);

    auto load_stage = [&](int st) {
        uint32_t base = sbase + (uint32_t)((st & 3) * STAGE_BYTES);
        int k0 = st * BK;
        #pragma unroll
        for (int i = 0; i < 2; i++) {
            int idx = tid + i * 256;
            int r = idx >> 2, c = idx & 3;
            cp16(base + r * (APH * 2) + c * 16, Ab + (size_t)r * QDIM + k0 + c * 8);
        }
        #pragma unroll
        for (int i = 0; i < 2; i++) {
            int idx = tid + i * 256;
            int r = idx >> 4, c = idx & 15;
            cp16(base + A_BYTES + r * (BPH * 2) + c * 16,
                 Bb + (size_t)(k0 + r) * ADIM + a0 + c * 8);
        }
    };

    wmma::fragment<wmma::accumulator, 16, 16, 16, float> acc[2][4];
    #pragma unroll
    for (int i = 0; i < 2; i++)
        #pragma unroll
        for (int j = 0; j < 4; j++)
            wmma::fill_fragment(acc[i][j], 0.0f);

    load_stage(0); CP_COMMIT();
    load_stage(1); CP_COMMIT();
    load_stage(2); CP_COMMIT();

    #pragma unroll 1
    for (int kt = 0; kt < NK; kt++) {
        CP_WAIT(2);
        __syncthreads();

        if (kt + 3 < NK) load_stage(kt + 3);
        CP_COMMIT();

        const __half* sA = (const __half*)(smc + (kt & 3) * STAGE_BYTES);
        const __half* sB = (const __half*)(smc + (kt & 3) * STAGE_BYTES + A_BYTES);

        #pragma unroll
        for (int kk = 0; kk < BK; kk += 16) {
            wmma::fragment<wmma::matrix_a, 16, 16, 16, __half, wmma::row_major> af[2];
            wmma::fragment<wmma::matrix_b, 16, 16, 16, __half, wmma::row_major> bf[4];
            #pragma unroll
            for (int i = 0; i < 2; i++)
                wmma::load_matrix_sync(af[i], sA + (wr * 32 + i * 16) * APH + kk, APH);
            #pragma unroll
            for (int j = 0; j < 4; j++)
                wmma::load_matrix_sync(bf[j], sB + kk * BPH + wc * 64 + j * 16, BPH);
            #pragma unroll
            for (int i = 0; i < 2; i++)
                #pragma unroll
                for (int j = 0; j < 4; j++)
                    wmma::mma_sync(acc[i][j], af[i], bf[j], acc[i][j]);
        }
    }

    __syncthreads();

    float* Epi = (float*)smc;
    #pragma unroll
    for (int i = 0; i < 2; i++)
        #pragma unroll
        for (int j = 0; j < 4; j++)
            wmma::store_matrix_sync(Epi + (wr * 32 + i * 16) * EPI_P + wc * 64 + j * 16,
                                    acc[i][j], EPI_P, wmma::mem_row_major);
    __syncthreads();

    const int r = tid & 127;
    const int half = tid >> 7;
    const float* er = Epi + r * EPI_P + half * 64;
    float s = 0.0f;
    #pragma unroll 8
    for (int j = 0; j < 64; j++) {
        int c = half * 64 + j;
        float v = er[j] + xs[c];
        s += fmaxf(v, 0.0f) * ws[c];
    }
    psum[r][half] = s;
    __syncthreads();
    if (tid < BM)
        g_part[(size_t)ntile * MROWS + row0 + tid] = psum[tid][0] + psum[tid][1];
}

// ======================= X2att = X @ W_ques + b_ques (fp16, pipelined) =======================
__global__ __launch_bounds__(256, 2)
void x2att_mma(const float* __restrict__ bias)
{
    extern __shared__ char smc[];

    const int tid  = threadIdx.x;
    const int warp = tid >> 5;
    const int wr   = warp & 3;
    const int wc   = warp >> 2;

    const int a0   = blockIdx.x * BN;
    const size_t row0 = (size_t)blockIdx.y * BM;

    const __half* Ab = g_xh + row0 * QDIM;
    const __half* Bb = g_wqh;
    const uint32_t sbase = smem_u32(smc);

    auto load_stage = [&](int st) {
        uint32_t base = sbase + (uint32_t)((st & 3) * STAGE_BYTES);
        int k0 = st * BK;
        #pragma unroll
        for (int i = 0; i < 2; i++) {
            int idx = tid + i * 256;
            int r = idx >> 2, c = idx & 3;
            cp16(base + r * (APH * 2) + c * 16, Ab + (size_t)r * QDIM + k0 + c * 8);
        }
        #pragma unroll
        for (int i = 0; i < 2; i++) {
            int idx = tid + i * 256;
            int r = idx >> 4, c = idx & 15;
            cp16(base + A_BYTES + r * (BPH * 2) + c * 16,
                 Bb + (size_t)(k0 + r) * ADIM + a0 + c * 8);
        }
    };

    wmma::fragment<wmma::accumulator, 16, 16, 16, float> acc[2][4];
    #pragma unroll
    for (int i = 0; i < 2; i++)
        #pragma unroll
        for (int j = 0; j < 4; j++)
            wmma::fill_fragment(acc[i][j], 0.0f);

    load_stage(0); CP_COMMIT();
    load_stage(1); CP_COMMIT();
    load_stage(2); CP_COMMIT();

    #pragma unroll 1
    for (int kt = 0; kt < NK; kt++) {
        CP_WAIT(2);
        __syncthreads();

        if (kt + 3 < NK) load_stage(kt + 3);
        CP_COMMIT();

        const __half* sA = (const __half*)(smc + (kt & 3) * STAGE_BYTES);
        const __half* sB = (const __half*)(smc + (kt & 3) * STAGE_BYTES + A_BYTES);

        #pragma unroll
        for (int kk = 0; kk < BK; kk += 16) {
            wmma::fragment<wmma::matrix_a, 16, 16, 16, __half, wmma::row_major> af[2];
            wmma::fragment<wmma::matrix_b, 16, 16, 16, __half, wmma::row_major> bf[4];
            #pragma unroll
            for (int i = 0; i < 2; i++)
                wmma::load_matrix_sync(af[i], sA + (wr * 32 + i * 16) * APH + kk, APH);
            #pragma unroll
            for (int j = 0; j < 4; j++)
                wmma::load_matrix_sync(bf[j], sB + kk * BPH + wc * 64 + j * 16, BPH);
            #pragma unroll
            for (int i = 0; i < 2; i++)
                #pragma unroll
                for (int j = 0; j < 4; j++)
                    wmma::mma_sync(acc[i][j], af[i], bf[j], acc[i][j]);
        }
    }

    __syncthreads();

    float* Epi = (float*)smc;
    #pragma unroll
    for (int i = 0; i < 2; i++)
        #pragma unroll
        for (int j = 0; j < 4; j++)
            wmma::store_matrix_sync(Epi + (wr * 32 + i * 16) * EPI_P + wc * 64 + j * 16,
                                    acc[i][j], EPI_P, wmma::mem_row_major);
    __syncthreads();

    for (int e = tid; e < BM * BN; e += 256) {
        int r = e >> 7, c = e & 127;
        g_x2att[(row0 + r) * ADIM + a0 + c] = Epi[r * EPI_P + c] + bias[a0 + c];
    }
}

// ======================= softmax + attend =======================
__global__ void softmax_k()
{
    __shared__ float red[256];
    const int b = blockIdx.x, t = threadIdx.x;
    float v0 = 0.0f, v1 = 0.0f;
    #pragma unroll
    for (int p = 0; p < 8; p++) {
        const float* P = g_part + (size_t)p * MROWS + (size_t)b * NSEQ;
        v0 += P[t]; v1 += P[t + 256];
    }
    red[t] = fmaxf(v0, v1);
    __syncthreads();
    for (int s = 128; s > 0; s >>= 1) { if (t < s) red[t] = fmaxf(red[t], red[t + s]); __syncthreads(); }
    float m = red[0];
    __syncthreads();
    float e0 = __expf(v0 - m), e1 = __expf(v1 - m);
    red[t] = e0 + e1;
    __syncthreads();
    for (int s = 128; s > 0; s >>= 1) { if (t < s) red[t] += red[t + s]; __syncthreads(); }
    float inv = 1.0f / red[0];
    g_w[b * NSEQ + t]       = e0 * inv;
    g_w[b * NSEQ + t + 256] = e1 * inv;
}

// reads fp16 Y scratch
__global__ __launch_bounds__(128)
void attend_k(float* __restrict__ out)
{
    __shared__ float w[NSEQ];
    const int b = blockIdx.y;
    const int v = blockIdx.x * 1024 + threadIdx.x * 8;

    for (int i = threadIdx.x; i < NSEQ; i += 128) w[i] = g_w[b * NSEQ + i];
    __syncthreads();

    const __half* Yb = g_yh + (size_t)b * NSEQ * VDIM + v;
    float acc[8] = {0.f};
    #pragma unroll 4
    for (int n = 0; n < NSEQ; n++) {
        uint4 p = *(const uint4*)(Yb + (size_t)n * VDIM);
        float wn = w[n];
        float2 f0 = __half22float2(*(__half2*)&p.x);
        float2 f1 = __half22float2(*(__half2*)&p.y);
        float2 f2 = __half22float2(*(__half2*)&p.z);
        float2 f3 = __half22float2(*(__half2*)&p.w);
        acc[0] += wn * f0.x; acc[1] += wn * f0.y;
        acc[2] += wn * f1.x; acc[3] += wn * f1.y;
        acc[4] += wn * f2.x; acc[5] += wn * f2.y;
        acc[6] += wn * f3.x; acc[7] += wn * f3.y;
    }
    float4 o0 = make_float4(acc[0], acc[1], acc[2], acc[3]);
    float4 o1 = make_float4(acc[4], acc[5], acc[6], acc[7]);
    *(float4*)(out + (size_t)b * VDIM + v)     = o0;
    *(float4*)(out + (size_t)b * VDIM + v + 4) = o1;
}

// ======================= launch =======================
extern "C" void kernel_launch(void* const* d_in, const int* in_sizes, int n_in,
                              void* d_out, int out_size)
{
    const float* X      = (const float*)d_in[0];
    const float* Y      = (const float*)d_in[1];
    const float* W_vis  = (const float*)d_in[2];
    const float* W_ques = (const float*)d_in[3];
    const float* b_ques = (const float*)d_in[4];
    const float* W_map  = (const float*)d_in[5];
    // d_in[6] = b_map: cancels under softmax shift-invariance.
    float* out = (float*)d_out;

    cudaFuncSetAttribute(x2att_mma,  cudaFuncAttributeMaxDynamicSharedMemorySize, (int)DSMEM);
    cudaFuncSetAttribute(logits_mma, cudaFuncAttributeMaxDynamicSharedMemorySize, (int)DSMEM);

    cvt_y <<<(size_t)MROWS * VDIM / (256 * 8), 256>>>(Y);
    cvt_w <<<(size_t)VDIM * ADIM / (256 * 8), 256>>>(W_vis);
    cvt_x <<<(size_t)BATCH * QDIM / (256 * 8), 256>>>(X);
    cvt_wq<<<(size_t)QDIM * ADIM / (256 * 8), 256>>>(W_ques);
    x2att_mma<<<dim3(ADIM / BN, BATCH / BM), 256, DSMEM>>>(b_ques);
    logits_mma<<<dim3(ADIM / BN, MROWS / BM), 256, DSMEM>>>(W_map);
    softmax_k<<<BATCH, 256>>>();
    attend_k<<<dim3(VDIM / 1024, BATCH), 128>>>(out);
}

// round 13
// speedup vs baseline: 1.3199x; 1.0042x over previous
#include <cuda_runtime.h>
#include <cuda_fp16.h>
#include <mma.h>
#include <cstdint>

using namespace nvcuda;

#define BATCH 256
#define NSEQ  512
#define QDIM  2048
#define VDIM  2048
#define ADIM  1024
#define MROWS (BATCH * NSEQ)   // 131072

// ---- scratch (module-scope device arrays; no runtime allocation) ----
__device__ __half g_yh[(size_t)MROWS * VDIM];      // 512 MB, Y in fp16
__device__ __half g_wvh[(size_t)VDIM * ADIM];      // 4 MB, W_vis in fp16
__device__ __half g_xh[(size_t)BATCH * QDIM];      // 1 MB, X in fp16
__device__ __half g_wqh[(size_t)QDIM * ADIM];      // 4 MB, W_ques in fp16
__device__ float  g_x2att[BATCH * ADIM];           // 1 MB
__device__ float  g_part[8 * MROWS];               // 4 MB logit partials
__device__ float  g_w[BATCH * NSEQ];               // (unused placeholder kept for layout stability)

// ======================= async-copy helpers =======================
__device__ __forceinline__ uint32_t smem_u32(const void* p) {
    uint32_t a;
    asm("{ .reg .u64 t; cvta.to.shared.u64 t, %1; cvt.u32.u64 %0, t; }" : "=r"(a) : "l"(p));
    return a;
}
__device__ __forceinline__ void cp16(uint32_t dst, const void* g) {
    asm volatile("cp.async.cg.shared.global [%0], [%1], 16;" :: "r"(dst), "l"(g));
}
#define CP_COMMIT() asm volatile("cp.async.commit_group;" ::: "memory")
#define CP_WAIT(n)  asm volatile("cp.async.wait_group %0;" :: "n"(n) : "memory")

// ======================= fp32 -> fp16 conversion passes =======================
__device__ __forceinline__ void cvt8(const float* __restrict__ src, __half* __restrict__ dst, size_t i)
{
    float4 v0 = *(const float4*)(src + i);
    float4 v1 = *(const float4*)(src + i + 4);
    __half2 h0 = __floats2half2_rn(v0.x, v0.y);
    __half2 h1 = __floats2half2_rn(v0.z, v0.w);
    __half2 h2 = __floats2half2_rn(v1.x, v1.y);
    __half2 h3 = __floats2half2_rn(v1.z, v1.w);
    uint4 packed;
    packed.x = *(uint32_t*)&h0; packed.y = *(uint32_t*)&h1;
    packed.z = *(uint32_t*)&h2; packed.w = *(uint32_t*)&h3;
    *(uint4*)(dst + i) = packed;
}

__global__ __launch_bounds__(256) void cvt_y(const float* __restrict__ Y)
{ cvt8(Y, g_yh, ((size_t)blockIdx.x * 256 + threadIdx.x) * 8); }

// one kernel for W_vis + X + W_ques (region boundaries divide 2048-elem blocks exactly)
__global__ __launch_bounds__(256)
void cvt_small(const float* __restrict__ Wv, const float* __restrict__ X,
               const float* __restrict__ Wq)
{
    const size_t n1 = (size_t)VDIM * ADIM;                 // 2M
    const size_t n2 = n1 + (size_t)BATCH * QDIM;           // +0.5M
    size_t i = ((size_t)blockIdx.x * 256 + threadIdx.x) * 8;
    if (i < n1)       cvt8(Wv, g_wvh, i);
    else if (i < n2)  cvt8(X,  g_xh,  i - n1);
    else              cvt8(Wq, g_wqh, i - n2);
}

// ======================= shared GEMM tiling constants =======================
constexpr int BM = 128, BN = 128, BK = 32;
constexpr int NK = QDIM / BK;                 // 64
constexpr int APH = 40;                       // A pitch in halves (80 B rows)
constexpr int BPH = 136;                      // B pitch in halves (272 B rows)
constexpr int A_BYTES = BM * APH * 2;         // 10240
constexpr int B_BYTES = BK * BPH * 2;         // 8704
constexpr int STAGE_BYTES = A_BYTES + B_BYTES;  // 18944
constexpr int EPI_P = BN + 4;
constexpr size_t DSMEM_GEMM = (size_t)4 * STAGE_BYTES;            // 75776
constexpr size_t DSMEM_EPI  = (size_t)BM * EPI_P * 4;             // 67584
constexpr size_t DSMEM = DSMEM_GEMM > DSMEM_EPI ? DSMEM_GEMM : DSMEM_EPI;

// ======================= fused logits GEMM (R8/R12-proven, unchanged) =======================
// part[nt, m] = sum_a relu( (Y @ W_vis)[m, a] + x2att[b(m), a] ) * W_map[a]
__global__ __launch_bounds__(256, 2)
void logits_mma(const float* __restrict__ Wmap)
{
    extern __shared__ char smc[];
    __shared__ float xs[BN], ws[BN];
    __shared__ float psum[BM][2];

    const int tid  = threadIdx.x;
    const int warp = tid >> 5;
    const int wr   = warp & 3;
    const int wc   = warp >> 2;

    const int ntile = blockIdx.x;       // 0..7 fastest (Y-tile L2 reuse)
    const int mtile = blockIdx.y;       // 0..1023
    const int a0    = ntile * BN;
    const size_t row0 = (size_t)mtile * BM;
    const int b     = mtile >> 2;

    if (tid < BN) {
        xs[tid] = g_x2att[(size_t)b * ADIM + a0 + tid];
        ws[tid] = Wmap[a0 + tid];
    }

    const __half* Ab = g_yh + row0 * QDIM;
    const __half* Bb = g_wvh;
    const uint32_t sbase = smem_u32(smc);

    auto load_stage = [&](int st) {
        uint32_t base = sbase + (uint32_t)((st & 3) * STAGE_BYTES);
        int k0 = st * BK;
        #pragma unroll
        for (int i = 0; i < 2; i++) {
            int idx = tid + i * 256;
            int r = idx >> 2, c = idx & 3;
            cp16(base + r * (APH * 2) + c * 16, Ab + (size_t)r * QDIM + k0 + c * 8);
        }
        #pragma unroll
        for (int i = 0; i < 2; i++) {
            int idx = tid + i * 256;
            int r = idx >> 4, c = idx & 15;
            cp16(base + A_BYTES + r * (BPH * 2) + c * 16,
                 Bb + (size_t)(k0 + r) * ADIM + a0 + c * 8);
        }
    };

    wmma::fragment<wmma::accumulator, 16, 16, 16, float> acc[2][4];
    #pragma unroll
    for (int i = 0; i < 2; i++)
        #pragma unroll
        for (int j = 0; j < 4; j++)
            wmma::fill_fragment(acc[i][j], 0.0f);

    load_stage(0); CP_COMMIT();
    load_stage(1); CP_COMMIT();
    load_stage(2); CP_COMMIT();

    #pragma unroll 1
    for (int kt = 0; kt < NK; kt++) {
        CP_WAIT(2);
        __syncthreads();

        if (kt + 3 < NK) load_stage(kt + 3);
        CP_COMMIT();

        const __half* sA = (const __half*)(smc + (kt & 3) * STAGE_BYTES);
        const __half* sB = (const __half*)(smc + (kt & 3) * STAGE_BYTES + A_BYTES);

        #pragma unroll
        for (int kk = 0; kk < BK; kk += 16) {
            wmma::fragment<wmma::matrix_a, 16, 16, 16, __half, wmma::row_major> af[2];
            wmma::fragment<wmma::matrix_b, 16, 16, 16, __half, wmma::row_major> bf[4];
            #pragma unroll
            for (int i = 0; i < 2; i++)
                wmma::load_matrix_sync(af[i], sA + (wr * 32 + i * 16) * APH + kk, APH);
            #pragma unroll
            for (int j = 0; j < 4; j++)
                wmma::load_matrix_sync(bf[j], sB + kk * BPH + wc * 64 + j * 16, BPH);
            #pragma unroll
            for (int i = 0; i < 2; i++)
                #pragma unroll
                for (int j = 0; j < 4; j++)
                    wmma::mma_sync(acc[i][j], af[i], bf[j], acc[i][j]);
        }
    }

    __syncthreads();

    float* Epi = (float*)smc;
    #pragma unroll
    for (int i = 0; i < 2; i++)
        #pragma unroll
        for (int j = 0; j < 4; j++)
            wmma::store_matrix_sync(Epi + (wr * 32 + i * 16) * EPI_P + wc * 64 + j * 16,
                                    acc[i][j], EPI_P, wmma::mem_row_major);
    __syncthreads();

    const int r = tid & 127;
    const int half = tid >> 7;
    const float* er = Epi + r * EPI_P + half * 64;
    float s = 0.0f;
    #pragma unroll 8
    for (int j = 0; j < 64; j++) {
        int c = half * 64 + j;
        float v = er[j] + xs[c];
        s += fmaxf(v, 0.0f) * ws[c];
    }
    psum[r][half] = s;
    __syncthreads();
    if (tid < BM)
        g_part[(size_t)ntile * MROWS + row0 + tid] = psum[tid][0] + psum[tid][1];
}

// ======================= X2att = X @ W_ques + b_ques (fp16, pipelined) =======================
__global__ __launch_bounds__(256, 2)
void x2att_mma(const float* __restrict__ bias)
{
    extern __shared__ char smc[];

    const int tid  = threadIdx.x;
    const int warp = tid >> 5;
    const int wr   = warp & 3;
    const int wc   = warp >> 2;

    const int a0   = blockIdx.x * BN;
    const size_t row0 = (size_t)blockIdx.y * BM;

    const __half* Ab = g_xh + row0 * QDIM;
    const __half* Bb = g_wqh;
    const uint32_t sbase = smem_u32(smc);

    auto load_stage = [&](int st) {
        uint32_t base = sbase + (uint32_t)((st & 3) * STAGE_BYTES);
        int k0 = st * BK;
        #pragma unroll
        for (int i = 0; i < 2; i++) {
            int idx = tid + i * 256;
            int r = idx >> 2, c = idx & 3;
            cp16(base + r * (APH * 2) + c * 16, Ab + (size_t)r * QDIM + k0 + c * 8);
        }
        #pragma unroll
        for (int i = 0; i < 2; i++) {
            int idx = tid + i * 256;
            int r = idx >> 4, c = idx & 15;
            cp16(base + A_BYTES + r * (BPH * 2) + c * 16,
                 Bb + (size_t)(k0 + r) * ADIM + a0 + c * 8);
        }
    };

    wmma::fragment<wmma::accumulator, 16, 16, 16, float> acc[2][4];
    #pragma unroll
    for (int i = 0; i < 2; i++)
        #pragma unroll
        for (int j = 0; j < 4; j++)
            wmma::fill_fragment(acc[i][j], 0.0f);

    load_stage(0); CP_COMMIT();
    load_stage(1); CP_COMMIT();
    load_stage(2); CP_COMMIT();

    #pragma unroll 1
    for (int kt = 0; kt < NK; kt++) {
        CP_WAIT(2);
        __syncthreads();

        if (kt + 3 < NK) load_stage(kt + 3);
        CP_COMMIT();

        const __half* sA = (const __half*)(smc + (kt & 3) * STAGE_BYTES);
        const __half* sB = (const __half*)(smc + (kt & 3) * STAGE_BYTES + A_BYTES);

        #pragma unroll
        for (int kk = 0; kk < BK; kk += 16) {
            wmma::fragment<wmma::matrix_a, 16, 16, 16, __half, wmma::row_major> af[2];
            wmma::fragment<wmma::matrix_b, 16, 16, 16, __half, wmma::row_major> bf[4];
            #pragma unroll
            for (int i = 0; i < 2; i++)
                wmma::load_matrix_sync(af[i], sA + (wr * 32 + i * 16) * APH + kk, APH);
            #pragma unroll
            for (int j = 0; j < 4; j++)
                wmma::load_matrix_sync(bf[j], sB + kk * BPH + wc * 64 + j * 16, BPH);
            #pragma unroll
            for (int i = 0; i < 2; i++)
                #pragma unroll
                for (int j = 0; j < 4; j++)
                    wmma::mma_sync(acc[i][j], af[i], bf[j], acc[i][j]);
        }
    }

    __syncthreads();

    float* Epi = (float*)smc;
    #pragma unroll
    for (int i = 0; i < 2; i++)
        #pragma unroll
        for (int j = 0; j < 4; j++)
            wmma::store_matrix_sync(Epi + (wr * 32 + i * 16) * EPI_P + wc * 64 + j * 16,
                                    acc[i][j], EPI_P, wmma::mem_row_major);
    __syncthreads();

    for (int e = tid; e < BM * BN; e += 256) {
        int r = e >> 7, c = e & 127;
        g_x2att[(row0 + r) * ADIM + a0 + c] = Epi[r * EPI_P + c] + bias[a0 + c];
    }
}

// ======================= fused softmax + attend (one block per batch) =======================
__global__ __launch_bounds__(256)
void attend_k(float* __restrict__ out)
{
    __shared__ float w[NSEQ];
    __shared__ float red[256];
    const int b = blockIdx.x;
    const int t = threadIdx.x;

    // sum logit partials over the 8 att-tiles
    float v0 = 0.0f, v1 = 0.0f;
    #pragma unroll
    for (int p = 0; p < 8; p++) {
        const float* P = g_part + (size_t)p * MROWS + (size_t)b * NSEQ;
        v0 += P[t]; v1 += P[t + 256];
    }
    // softmax over n (512 values)
    red[t] = fmaxf(v0, v1);
    __syncthreads();
    for (int s = 128; s > 0; s >>= 1) { if (t < s) red[t] = fmaxf(red[t], red[t + s]); __syncthreads(); }
    float m = red[0];
    __syncthreads();
    float e0 = __expf(v0 - m), e1 = __expf(v1 - m);
    red[t] = e0 + e1;
    __syncthreads();
    for (int s = 128; s > 0; s >>= 1) { if (t < s) red[t] += red[t + s]; __syncthreads(); }
    float inv = 1.0f / red[0];
    w[t]       = e0 * inv;
    w[t + 256] = e1 * inv;
    __syncthreads();

    // Y_attended[b] = w . Y[b]  (fp16 Y scratch, 8 v per thread => 2048 cols)
    const __half* Yb = g_yh + (size_t)b * NSEQ * VDIM + t * 8;
    float acc[8] = {0.f};
    #pragma unroll 4
    for (int n = 0; n < NSEQ; n++) {
        uint4 p = *(const uint4*)(Yb + (size_t)n * VDIM);
        float wn = w[n];
        float2 f0 = __half22float2(*(__half2*)&p.x);
        float2 f1 = __half22float2(*(__half2*)&p.y);
        float2 f2 = __half22float2(*(__half2*)&p.z);
        float2 f3 = __half22float2(*(__half2*)&p.w);
        acc[0] += wn * f0.x; acc[1] += wn * f0.y;
        acc[2] += wn * f1.x; acc[3] += wn * f1.y;
        acc[4] += wn * f2.x; acc[5] += wn * f2.y;
        acc[6] += wn * f3.x; acc[7] += wn * f3.y;
    }
    float4 o0 = make_float4(acc[0], acc[1], acc[2], acc[3]);
    float4 o1 = make_float4(acc[4], acc[5], acc[6], acc[7]);
    *(float4*)(out + (size_t)b * VDIM + t * 8)     = o0;
    *(float4*)(out + (size_t)b * VDIM + t * 8 + 4) = o1;
}

// ======================= launch =======================
extern "C" void kernel_launch(void* const* d_in, const int* in_sizes, int n_in,
                              void* d_out, int out_size)
{
    const float* X      = (const float*)d_in[0];
    const float* Y      = (const float*)d_in[1];
    const float* W_vis  = (const float*)d_in[2];
    const float* W_ques = (const float*)d_in[3];
    const float* b_ques = (const float*)d_in[4];
    const float* W_map  = (const float*)d_in[5];
    // d_in[6] = b_map: cancels under softmax shift-invariance.
    float* out = (float*)d_out;

    cudaFuncSetAttribute(x2att_mma,  cudaFuncAttributeMaxDynamicSharedMemorySize, (int)DSMEM);
    cudaFuncSetAttribute(logits_mma, cudaFuncAttributeMaxDynamicSharedMemorySize, (int)DSMEM);

    const size_t small_total = (size_t)VDIM * ADIM + (size_t)BATCH * QDIM + (size_t)QDIM * ADIM;
    cvt_y    <<<(size_t)MROWS * VDIM / (256 * 8), 256>>>(Y);
    cvt_small<<<small_total / (256 * 8), 256>>>(W_vis, X, W_ques);
    x2att_mma<<<dim3(ADIM / BN, BATCH / BM), 256, DSMEM>>>(b_ques);
    logits_mma<<<dim3(ADIM / BN, MROWS / BM), 256, DSMEM>>>(W_map);
    attend_k<<<BATCH, 256>>>(out);
}